// round 12
// baseline (speedup 1.0000x reference)
#include <cuda_runtime.h>
#include <mma.h>
#include <cstdint>

using namespace nvcuda;

#define N_NODES 50000
#define MAX_E   800000
#define D 96
#define D4 (D/4)
#define GROWS 96                             // rows per gemm block
#define GTHREADS 192
#define GEMM_SMEM (3 * D * D * 4)            // xs + whi + wlo = 110592 B
#define NBLK ((N_NODES + 255) / 256)         // 196 scan blocks

// ---- device scratch (zero-init at load; k_agg restores counter zeros) ----
__device__ int   g_deg_out_i[N_NODES];
__device__ int   g_deg_in_i[N_NODES];
__device__ int   g_row_ptr[N_NODES + 1];
__device__ int   g_fill[N_NODES];
__device__ int   g_bsum[256];
__device__ int   g_csr_src[MAX_E];
__device__ float g_h[(size_t)N_NODES * D];   // (x@W) * inv_sqrt(deg_out)

// ---- degree kernels (split so each stream waits only on what it needs) ----
__global__ void k_deg_out(const int* __restrict__ src, int E) {
    int e = blockIdx.x * blockDim.x + threadIdx.x;
    if (e < E) atomicAdd(&g_deg_out_i[src[e]], 1);
}
__global__ void k_deg_in(const int* __restrict__ dst, int E) {
    int e = blockIdx.x * blockDim.x + threadIdx.x;
    if (e < E) atomicAdd(&g_deg_in_i[dst[e]], 1);
}

// ---- scan step 1: per-block exclusive scan of deg_in ----
__global__ void k_scan1() {
    __shared__ int sh[256];
    int i = blockIdx.x * 256 + threadIdx.x;
    int v = (i < N_NODES) ? g_deg_in_i[i] : 0;
    sh[threadIdx.x] = v;
    __syncthreads();
    #pragma unroll
    for (int off = 1; off < 256; off <<= 1) {
        int t = (threadIdx.x >= off) ? sh[threadIdx.x - off] : 0;
        __syncthreads();
        sh[threadIdx.x] += t;
        __syncthreads();
    }
    if (i < N_NODES) g_row_ptr[i] = sh[threadIdx.x] - v;
    if (threadIdx.x == 255) g_bsum[blockIdx.x] = sh[255];
}

// ---- scan steps 2+3 fused: every block scans the 196 block sums itself ----
__global__ void k_scan23(int E) {
    __shared__ int sh[256];
    int t = threadIdx.x;
    int v = (t < NBLK) ? g_bsum[t] : 0;
    sh[t] = v;
    __syncthreads();
    #pragma unroll
    for (int off = 1; off < 256; off <<= 1) {
        int u = (t >= off) ? sh[t - off] : 0;
        __syncthreads();
        sh[t] += u;
        __syncthreads();
    }
    int base = (blockIdx.x > 0) ? sh[blockIdx.x - 1] : 0;

    int i = blockIdx.x * 256 + t;
    if (i < N_NODES) {
        int p = g_row_ptr[i] + base;
        g_row_ptr[i] = p;
        g_fill[i] = p;
    }
    if (i == 0) g_row_ptr[N_NODES] = E;
}

// ---- kernel: bucket edges by dst ----
__global__ void k_fill(const int* __restrict__ src,
                       const int* __restrict__ dst, int E) {
    int e = blockIdx.x * blockDim.x + threadIdx.x;
    if (e < E) {
        int d = dst[e];
        int pos = atomicAdd(&g_fill[d], 1);
        g_csr_src[pos] = src[e];
    }
}

// ---- kernel: h = (x@W) * inv_sqrt(deg_out), tf32 TC, 3-term comp, smem W ----
// 96 rows/block, 6 warps; warp w owns rows [16w,16w+16), all 96 cols.
__global__ __launch_bounds__(GTHREADS)
void k_gemm(const float* __restrict__ x, const float* __restrict__ Wg) {
    extern __shared__ float smem[];
    float* xs  = smem;               // [96][96] x tile (raw fp32)
    float* whi = smem + D * D;       // [96][96] W hi (tf32)
    float* wlo = smem + 2 * D * D;   // [96][96] W lo (tf32)

    const int tid = threadIdx.x;
    const int rbase = blockIdx.x * GROWS;

    // stage x tile (zero-padded) and raw W
    for (int i = tid; i < GROWS * D4; i += GTHREADS) {
        int r = i / D4, c = i % D4;
        int g = rbase + r;
        float4 v = make_float4(0.f, 0.f, 0.f, 0.f);
        if (g < N_NODES) v = ((const float4*)(x + (size_t)g * D))[c];
        ((float4*)xs)[i] = v;
        ((float4*)whi)[i] = ((const float4*)Wg)[i];
    }
    __syncthreads();

    // split W into tf32 hi/lo in-place (each element touched by one thread)
    for (int i = tid; i < D * D; i += GTHREADS) {
        float f  = whi[i];
        float hi = wmma::__float_to_tf32(f);
        whi[i] = hi;
        wlo[i] = wmma::__float_to_tf32(f - hi);
    }
    __syncthreads();

    const int warp = tid >> 5;

    wmma::fragment<wmma::accumulator, 16, 16, 8, float> acc[6];
    #pragma unroll
    for (int j = 0; j < 6; j++) wmma::fill_fragment(acc[j], 0.0f);

    #pragma unroll
    for (int k = 0; k < D; k += 8) {
        wmma::fragment<wmma::matrix_a, 16, 16, 8, wmma::precision::tf32,
                       wmma::row_major> a_hi, a_lo;
        wmma::load_matrix_sync(a_hi, xs + warp * 16 * D + k, D);
        #pragma unroll
        for (int t = 0; t < a_hi.num_elements; t++) {
            float f  = a_hi.x[t];
            float hi = wmma::__float_to_tf32(f);
            a_hi.x[t] = hi;
            a_lo.x[t] = wmma::__float_to_tf32(f - hi);
        }
        #pragma unroll
        for (int j = 0; j < 6; j++) {
            wmma::fragment<wmma::matrix_b, 16, 16, 8, wmma::precision::tf32,
                           wmma::row_major> b_hi, b_lo;
            wmma::load_matrix_sync(b_hi, whi + k * D + j * 16, D);
            wmma::load_matrix_sync(b_lo, wlo + k * D + j * 16, D);
            wmma::mma_sync(acc[j], a_hi, b_lo, acc[j]);
            wmma::mma_sync(acc[j], a_lo, b_hi, acc[j]);
            wmma::mma_sync(acc[j], a_hi, b_hi, acc[j]);
        }
    }

    __syncthreads();   // done reading xs
    #pragma unroll
    for (int j = 0; j < 6; j++)
        wmma::store_matrix_sync(xs + warp * 16 * D + j * 16, acc[j], D,
                                wmma::mem_row_major);
    __syncthreads();

    // epilogue: scale by inv_sqrt(deg_out), write h
    for (int i = tid; i < GROWS * D4; i += GTHREADS) {
        int r = i / D4, c = i % D4;
        int row = rbase + r;
        if (row < N_NODES) {
            float dg  = (float)g_deg_out_i[row];
            float inv = dg > 0.f ? rsqrtf(dg) : 0.f;
            float4 v = ((float4*)xs)[i];
            float4 o = make_float4(v.x * inv, v.y * inv, v.z * inv, v.w * inv);
            ((float4*)&g_h[(size_t)row * D])[c] = o;
        }
    }
}

// ---- kernel: aggregate per dst node (one warp/node, float4 lanes) ----
__global__ __launch_bounds__(256)
void k_agg(const float* __restrict__ b, float* __restrict__ out) {
    int warp = (blockIdx.x * blockDim.x + threadIdx.x) >> 5;
    int lane = threadIdx.x & 31;
    if (warp >= N_NODES) return;

    int beg = g_row_ptr[warp];
    int end = g_row_ptr[warp + 1];

    if (lane < D4) {
        float4 a = make_float4(0.f, 0.f, 0.f, 0.f);
        const float4* hbase = (const float4*)g_h;
        int j = beg;
        for (; j + 3 < end; j += 4) {
            int s0 = __ldg(&g_csr_src[j]);
            int s1 = __ldg(&g_csr_src[j + 1]);
            int s2 = __ldg(&g_csr_src[j + 2]);
            int s3 = __ldg(&g_csr_src[j + 3]);
            float4 v0 = __ldg(hbase + (size_t)s0 * D4 + lane);
            float4 v1 = __ldg(hbase + (size_t)s1 * D4 + lane);
            float4 v2 = __ldg(hbase + (size_t)s2 * D4 + lane);
            float4 v3 = __ldg(hbase + (size_t)s3 * D4 + lane);
            a.x += (v0.x + v1.x) + (v2.x + v3.x);
            a.y += (v0.y + v1.y) + (v2.y + v3.y);
            a.z += (v0.z + v1.z) + (v2.z + v3.z);
            a.w += (v0.w + v1.w) + (v2.w + v3.w);
        }
        for (; j < end; j++) {
            int s = __ldg(&g_csr_src[j]);
            float4 v = __ldg(hbase + (size_t)s * D4 + lane);
            a.x += v.x; a.y += v.y; a.z += v.z; a.w += v.w;
        }

        float dg  = (float)(end - beg);
        float inv = dg > 0.f ? rsqrtf(dg) : 0.f;
        float4 bb = ((const float4*)b)[lane];
        float4 o  = make_float4(a.x * inv + bb.x, a.y * inv + bb.y,
                                a.z * inv + bb.z, a.w * inv + bb.w);
        ((float4*)(out + (size_t)warp * D))[lane] = o;
    }

    // restore zero-invariant for the next graph replay
    if (lane == 30) {
        g_deg_in_i[warp]  = 0;
        g_deg_out_i[warp] = 0;
    }
}

extern "C" void kernel_launch(void* const* d_in, const int* in_sizes, int n_in,
                              void* d_out, int out_size) {
    const float* x   = (const float*)d_in[0];
    const float* W   = (const float*)d_in[1];
    const float* b   = (const float*)d_in[2];
    const int*   src = (const int*)d_in[3];
    const int*   dst = (const int*)d_in[4];
    float* out = (float*)d_out;
    const int E = in_sizes[3];

    cudaFuncSetAttribute(k_gemm, cudaFuncAttributeMaxDynamicSharedMemorySize,
                         GEMM_SMEM);

    cudaStream_t s2;
    cudaStreamCreateWithFlags(&s2, cudaStreamNonBlocking);
    cudaEvent_t ev_root, ev_gemm;
    cudaEventCreateWithFlags(&ev_root, cudaEventDisableTiming);
    cudaEventCreateWithFlags(&ev_gemm, cudaEventDisableTiming);

    // fork: s2 = deg_out -> gemm;  main = deg_in -> scan -> fill
    cudaEventRecord(ev_root, 0);
    cudaStreamWaitEvent(s2, ev_root, 0);

    k_deg_out<<<(E + 255) / 256, 256, 0, s2>>>(src, E);
    k_gemm<<<(N_NODES + GROWS - 1) / GROWS, GTHREADS, GEMM_SMEM, s2>>>(x, W);
    cudaEventRecord(ev_gemm, s2);

    k_deg_in<<<(E + 255) / 256, 256>>>(dst, E);
    k_scan1<<<NBLK, 256>>>();
    k_scan23<<<NBLK, 256>>>(E);
    k_fill<<<(E + 255) / 256, 256>>>(src, dst, E);

    cudaStreamWaitEvent(0, ev_gemm, 0);
    long long agg_threads = (long long)N_NODES * 32;
    k_agg<<<(int)((agg_threads + 255) / 256), 256>>>(b, out);
}

// round 13
// speedup vs baseline: 1.2769x; 1.2769x over previous
#include <cuda_runtime.h>
#include <cstdint>

#define N_NODES 50000
#define MAX_E   800000
#define D 96
#define D4 (D/4)
#define TILE_ROWS 48
#define TX 24
#define TY 8
#define RPT 6
#define KH 48                                // k-phase half
#define NBLK ((N_NODES + 255) / 256)         // 196 scan blocks

// ---- device scratch (zero-init at load; k_agg restores counter zeros) ----
__device__ int   g_deg_out_i[N_NODES];
__device__ int   g_deg_in_i[N_NODES];
__device__ int   g_row_ptr[N_NODES + 1];
__device__ int   g_fill[N_NODES];
__device__ int   g_bsum[256];
__device__ int   g_csr_src[MAX_E];
__device__ float g_h[(size_t)N_NODES * D];   // (x@W) * inv_sqrt(deg_out)

// ---- degree kernels (split so each stream waits only on what it needs) ----
__global__ void k_deg_out(const int* __restrict__ src, int E) {
    int e = blockIdx.x * blockDim.x + threadIdx.x;
    if (e < E) atomicAdd(&g_deg_out_i[src[e]], 1);
}
__global__ void k_deg_in(const int* __restrict__ dst, int E) {
    int e = blockIdx.x * blockDim.x + threadIdx.x;
    if (e < E) atomicAdd(&g_deg_in_i[dst[e]], 1);
}

// ---- scan step 1: per-block exclusive scan of deg_in ----
__global__ void k_scan1() {
    __shared__ int sh[256];
    int i = blockIdx.x * 256 + threadIdx.x;
    int v = (i < N_NODES) ? g_deg_in_i[i] : 0;
    sh[threadIdx.x] = v;
    __syncthreads();
    #pragma unroll
    for (int off = 1; off < 256; off <<= 1) {
        int t = (threadIdx.x >= off) ? sh[threadIdx.x - off] : 0;
        __syncthreads();
        sh[threadIdx.x] += t;
        __syncthreads();
    }
    if (i < N_NODES) g_row_ptr[i] = sh[threadIdx.x] - v;
    if (threadIdx.x == 255) g_bsum[blockIdx.x] = sh[255];
}

// ---- scan steps 2+3 fused: every block scans the 196 block sums itself ----
__global__ void k_scan23(int E) {
    __shared__ int sh[256];
    int t = threadIdx.x;
    int v = (t < NBLK) ? g_bsum[t] : 0;
    sh[t] = v;
    __syncthreads();
    #pragma unroll
    for (int off = 1; off < 256; off <<= 1) {
        int u = (t >= off) ? sh[t - off] : 0;
        __syncthreads();
        sh[t] += u;
        __syncthreads();
    }
    int base = (blockIdx.x > 0) ? sh[blockIdx.x - 1] : 0;

    int i = blockIdx.x * 256 + t;
    if (i < N_NODES) {
        int p = g_row_ptr[i] + base;
        g_row_ptr[i] = p;
        g_fill[i] = p;
    }
    if (i == 0) g_row_ptr[N_NODES] = E;
}

// ---- kernel: bucket edges by dst ----
__global__ void k_fill(const int* __restrict__ src,
                       const int* __restrict__ dst, int E) {
    int e = blockIdx.x * blockDim.x + threadIdx.x;
    if (e < E) {
        int d = dst[e];
        int pos = atomicAdd(&g_fill[d], 1);
        g_csr_src[pos] = src[e];
    }
}

// ---- kernel: h = (x@W) * inv_sqrt(deg_out)  (R7 gemm, 4-blocks/SM target) ----
__global__ __launch_bounds__(TX * TY, 4)
void k_gemm(const float* __restrict__ x, const float* __restrict__ Wg) {
    __shared__ float Ws[KH * D];          // 18432 B
    __shared__ float xs[TILE_ROWS * D];   // 18432 B  (36864 B total)

    const int tid = threadIdx.y * TX + threadIdx.x;
    const int nth = TX * TY;              // 192
    const int rbase = blockIdx.x * TILE_ROWS;

    for (int i = tid; i < TILE_ROWS * D4; i += nth) {
        int r = i / D4, c = i % D4;
        int g = rbase + r;
        float4 v = make_float4(0.f, 0.f, 0.f, 0.f);
        if (g < N_NODES) v = ((const float4*)(x + (size_t)g * D))[c];
        ((float4*)xs)[r * D4 + c] = v;
    }

    float4 acc[RPT];
    #pragma unroll
    for (int r = 0; r < RPT; r++) acc[r] = make_float4(0.f, 0.f, 0.f, 0.f);

    const int tx4 = threadIdx.x * 4;
    const int ry  = threadIdx.y * RPT;

    #pragma unroll
    for (int p = 0; p < 2; p++) {
        __syncthreads();
        for (int i = tid; i < KH * D4; i += nth)
            ((float4*)Ws)[i] = ((const float4*)Wg)[p * KH * D4 + i];
        __syncthreads();

        #pragma unroll
        for (int kk = 0; kk < KH; kk += 4) {
            float4 w0 = *(const float4*)&Ws[(kk + 0) * D + tx4];
            float4 w1 = *(const float4*)&Ws[(kk + 1) * D + tx4];
            float4 w2 = *(const float4*)&Ws[(kk + 2) * D + tx4];
            float4 w3 = *(const float4*)&Ws[(kk + 3) * D + tx4];
            #pragma unroll
            for (int r = 0; r < RPT; r++) {
                float4 xv = *(const float4*)&xs[(ry + r) * D + p * KH + kk];
                acc[r].x += xv.x * w0.x + xv.y * w1.x + xv.z * w2.x + xv.w * w3.x;
                acc[r].y += xv.x * w0.y + xv.y * w1.y + xv.z * w2.y + xv.w * w3.y;
                acc[r].z += xv.x * w0.z + xv.y * w1.z + xv.z * w2.z + xv.w * w3.z;
                acc[r].w += xv.x * w0.w + xv.y * w1.w + xv.z * w2.w + xv.w * w3.w;
            }
        }
    }

    #pragma unroll
    for (int r = 0; r < RPT; r++) {
        int row = rbase + ry + r;
        if (row < N_NODES) {
            float dg  = (float)g_deg_out_i[row];
            float inv = dg > 0.f ? rsqrtf(dg) : 0.f;
            float4 o = make_float4(acc[r].x * inv, acc[r].y * inv,
                                   acc[r].z * inv, acc[r].w * inv);
            *(float4*)&g_h[(size_t)row * D + tx4] = o;
        }
    }
}

// ---- kernel: aggregate per dst node (one warp/node, float4 lanes) ----
__global__ __launch_bounds__(256)
void k_agg(const float* __restrict__ b, float* __restrict__ out) {
    int warp = (blockIdx.x * blockDim.x + threadIdx.x) >> 5;
    int lane = threadIdx.x & 31;
    if (warp >= N_NODES) return;

    int beg = g_row_ptr[warp];
    int end = g_row_ptr[warp + 1];

    if (lane < D4) {
        float4 a = make_float4(0.f, 0.f, 0.f, 0.f);
        const float4* hbase = (const float4*)g_h;
        int j = beg;
        for (; j + 3 < end; j += 4) {
            int s0 = __ldg(&g_csr_src[j]);
            int s1 = __ldg(&g_csr_src[j + 1]);
            int s2 = __ldg(&g_csr_src[j + 2]);
            int s3 = __ldg(&g_csr_src[j + 3]);
            float4 v0 = __ldg(hbase + (size_t)s0 * D4 + lane);
            float4 v1 = __ldg(hbase + (size_t)s1 * D4 + lane);
            float4 v2 = __ldg(hbase + (size_t)s2 * D4 + lane);
            float4 v3 = __ldg(hbase + (size_t)s3 * D4 + lane);
            a.x += (v0.x + v1.x) + (v2.x + v3.x);
            a.y += (v0.y + v1.y) + (v2.y + v3.y);
            a.z += (v0.z + v1.z) + (v2.z + v3.z);
            a.w += (v0.w + v1.w) + (v2.w + v3.w);
        }
        for (; j < end; j++) {
            int s = __ldg(&g_csr_src[j]);
            float4 v = __ldg(hbase + (size_t)s * D4 + lane);
            a.x += v.x; a.y += v.y; a.z += v.z; a.w += v.w;
        }

        float dg  = (float)(end - beg);
        float inv = dg > 0.f ? rsqrtf(dg) : 0.f;
        float4 bb = ((const float4*)b)[lane];
        float4 o  = make_float4(a.x * inv + bb.x, a.y * inv + bb.y,
                                a.z * inv + bb.z, a.w * inv + bb.w);
        ((float4*)(out + (size_t)warp * D))[lane] = o;
    }

    // restore zero-invariant for the next graph replay
    if (lane == 30) {
        g_deg_in_i[warp]  = 0;
        g_deg_out_i[warp] = 0;
    }
}

extern "C" void kernel_launch(void* const* d_in, const int* in_sizes, int n_in,
                              void* d_out, int out_size) {
    const float* x   = (const float*)d_in[0];
    const float* W   = (const float*)d_in[1];
    const float* b   = (const float*)d_in[2];
    const int*   src = (const int*)d_in[3];
    const int*   dst = (const int*)d_in[4];
    float* out = (float*)d_out;
    const int E = in_sizes[3];

    static bool attr_set = false;
    if (!attr_set) {
        // 4 blocks x 36.9KB = 147KB smem per SM -> ~66% of 228KB unified L1
        cudaFuncSetAttribute(k_gemm,
                             cudaFuncAttributePreferredSharedMemoryCarveout, 66);
        attr_set = true;
    }

    cudaStream_t s2;
    cudaStreamCreateWithFlags(&s2, cudaStreamNonBlocking);
    cudaEvent_t ev_root, ev_gemm;
    cudaEventCreateWithFlags(&ev_root, cudaEventDisableTiming);
    cudaEventCreateWithFlags(&ev_gemm, cudaEventDisableTiming);

    // fork: s2 = deg_out -> gemm;  main = deg_in -> scan -> fill
    cudaEventRecord(ev_root, 0);
    cudaStreamWaitEvent(s2, ev_root, 0);

    k_deg_out<<<(E + 255) / 256, 256, 0, s2>>>(src, E);
    k_gemm<<<(N_NODES + TILE_ROWS - 1) / TILE_ROWS, dim3(TX, TY), 0, s2>>>(x, W);
    cudaEventRecord(ev_gemm, s2);

    k_deg_in<<<(E + 255) / 256, 256>>>(dst, E);
    k_scan1<<<NBLK, 256>>>();
    k_scan23<<<NBLK, 256>>>(E);
    k_fill<<<(E + 255) / 256, 256>>>(src, dst, E);

    cudaStreamWaitEvent(0, ev_gemm, 0);
    long long agg_threads = (long long)N_NODES * 32;
    k_agg<<<(int)((agg_threads + 255) / 256), 256>>>(b, out);
}

// round 15
// speedup vs baseline: 1.3527x; 1.0593x over previous
#include <cuda_runtime.h>
#include <cuda_fp16.h>
#include <cstdint>

#define N_NODES 50000
#define MAX_E   800000
#define D 96
#define D4 (D/4)
#define D8 (D/4)                             // 24 uint2 (4 halves) per row
#define TILE_ROWS 48
#define TX 24
#define TY 8
#define RPT 6
#define KH 48                                // k-phase half
#define NBLK ((N_NODES + 255) / 256)         // 196 scan blocks

// ---- device scratch (zero-init at load; k_agg restores counter zeros) ----
__device__ int    g_deg_out_i[N_NODES];
__device__ int    g_deg_in_i[N_NODES];
__device__ float  g_inv_out[N_NODES];
__device__ int    g_row_ptr[N_NODES + 1];
__device__ int    g_fill[N_NODES];
__device__ int    g_bsum[256];
__device__ int    g_csr_src[MAX_E];
__device__ __half g_hh[(size_t)N_NODES * D]; // h = x@W, fp16 (unscaled)

// bit-cast helpers (register moves only)
__device__ __forceinline__ unsigned h2_to_u32(__half2 h) {
    return *reinterpret_cast<unsigned*>(&h);
}
__device__ __forceinline__ __half2 u32_to_h2(unsigned u) {
    return *reinterpret_cast<__half2*>(&u);
}

// ---- kernel: degree counts (counters pre-zeroed by invariant) ----
__global__ void k_deg(const int* __restrict__ src,
                      const int* __restrict__ dst, int E) {
    int e = blockIdx.x * blockDim.x + threadIdx.x;
    if (e < E) {
        atomicAdd(&g_deg_out_i[src[e]], 1);
        atomicAdd(&g_deg_in_i[dst[e]], 1);
    }
}

// ---- kernel: inv_out = rsqrt(deg_out) ----
__global__ void k_inv() {
    int i = blockIdx.x * blockDim.x + threadIdx.x;
    if (i < N_NODES) {
        float dg = (float)g_deg_out_i[i];
        g_inv_out[i] = dg > 0.f ? rsqrtf(dg) : 0.f;
    }
}

// ---- scan step 1: per-block exclusive scan of deg_in ----
__global__ void k_scan1() {
    __shared__ int sh[256];
    int i = blockIdx.x * 256 + threadIdx.x;
    int v = (i < N_NODES) ? g_deg_in_i[i] : 0;
    sh[threadIdx.x] = v;
    __syncthreads();
    #pragma unroll
    for (int off = 1; off < 256; off <<= 1) {
        int t = (threadIdx.x >= off) ? sh[threadIdx.x - off] : 0;
        __syncthreads();
        sh[threadIdx.x] += t;
        __syncthreads();
    }
    if (i < N_NODES) g_row_ptr[i] = sh[threadIdx.x] - v;
    if (threadIdx.x == 255) g_bsum[blockIdx.x] = sh[255];
}

// ---- scan steps 2+3 fused: every block scans the 196 block sums itself ----
__global__ void k_scan23(int E) {
    __shared__ int sh[256];
    int t = threadIdx.x;
    int v = (t < NBLK) ? g_bsum[t] : 0;
    sh[t] = v;
    __syncthreads();
    #pragma unroll
    for (int off = 1; off < 256; off <<= 1) {
        int u = (t >= off) ? sh[t - off] : 0;
        __syncthreads();
        sh[t] += u;
        __syncthreads();
    }
    int base = (blockIdx.x > 0) ? sh[blockIdx.x - 1] : 0;

    int i = blockIdx.x * 256 + t;
    if (i < N_NODES) {
        int p = g_row_ptr[i] + base;
        g_row_ptr[i] = p;
        g_fill[i] = p;
    }
    if (i == 0) g_row_ptr[N_NODES] = E;
}

// ---- kernel: bucket edges by dst ----
__global__ void k_fill(const int* __restrict__ src,
                       const int* __restrict__ dst, int E) {
    int e = blockIdx.x * blockDim.x + threadIdx.x;
    if (e < E) {
        int d = dst[e];
        int pos = atomicAdd(&g_fill[d], 1);
        g_csr_src[pos] = src[e];
    }
}

// ---- kernel: h = x@W  (fp32 compute, fp16 store; NO dependencies) ----
__global__ __launch_bounds__(TX * TY)
void k_gemm(const float* __restrict__ x, const float* __restrict__ Wg) {
    __shared__ float Ws[KH * D];          // 18432 B
    __shared__ float xs[TILE_ROWS * D];   // 18432 B

    const int tid = threadIdx.y * TX + threadIdx.x;
    const int nth = TX * TY;              // 192
    const int rbase = blockIdx.x * TILE_ROWS;

    for (int i = tid; i < TILE_ROWS * D4; i += nth) {
        int r = i / D4, c = i % D4;
        int g = rbase + r;
        float4 v = make_float4(0.f, 0.f, 0.f, 0.f);
        if (g < N_NODES) v = ((const float4*)(x + (size_t)g * D))[c];
        ((float4*)xs)[r * D4 + c] = v;
    }

    float4 acc[RPT];
    #pragma unroll
    for (int r = 0; r < RPT; r++) acc[r] = make_float4(0.f, 0.f, 0.f, 0.f);

    const int tx4 = threadIdx.x * 4;
    const int ry  = threadIdx.y * RPT;

    #pragma unroll
    for (int p = 0; p < 2; p++) {
        __syncthreads();
        for (int i = tid; i < KH * D4; i += nth)
            ((float4*)Ws)[i] = ((const float4*)Wg)[p * KH * D4 + i];
        __syncthreads();

        #pragma unroll
        for (int kk = 0; kk < KH; kk += 4) {
            float4 w0 = *(const float4*)&Ws[(kk + 0) * D + tx4];
            float4 w1 = *(const float4*)&Ws[(kk + 1) * D + tx4];
            float4 w2 = *(const float4*)&Ws[(kk + 2) * D + tx4];
            float4 w3 = *(const float4*)&Ws[(kk + 3) * D + tx4];
            #pragma unroll
            for (int r = 0; r < RPT; r++) {
                float4 xv = *(const float4*)&xs[(ry + r) * D + p * KH + kk];
                acc[r].x += xv.x * w0.x + xv.y * w1.x + xv.z * w2.x + xv.w * w3.x;
                acc[r].y += xv.x * w0.y + xv.y * w1.y + xv.z * w2.y + xv.w * w3.y;
                acc[r].z += xv.x * w0.z + xv.y * w1.z + xv.z * w2.z + xv.w * w3.z;
                acc[r].w += xv.x * w0.w + xv.y * w1.w + xv.z * w2.w + xv.w * w3.w;
            }
        }
    }

    #pragma unroll
    for (int r = 0; r < RPT; r++) {
        int row = rbase + ry + r;
        if (row < N_NODES) {
            __half2 h01 = __floats2half2_rn(acc[r].x, acc[r].y);
            __half2 h23 = __floats2half2_rn(acc[r].z, acc[r].w);
            uint2 u;
            u.x = h2_to_u32(h01);
            u.y = h2_to_u32(h23);
            ((uint2*)(g_hh + (size_t)row * D))[threadIdx.x] = u;
        }
    }
}

// ---- kernel: aggregate per dst: out[d] = inv_in[d]*Σ inv_out[s]*h[s] + b ----
__global__ __launch_bounds__(256)
void k_agg(const float* __restrict__ b, float* __restrict__ out) {
    int warp = (blockIdx.x * blockDim.x + threadIdx.x) >> 5;
    int lane = threadIdx.x & 31;
    if (warp >= N_NODES) return;

    int beg = g_row_ptr[warp];
    int end = g_row_ptr[warp + 1];

    if (lane < D8) {
        float4 a = make_float4(0.f, 0.f, 0.f, 0.f);
        const uint2* hb = (const uint2*)g_hh;   // 24 uint2 (4 halves) per row
        int j = beg;
        for (; j + 3 < end; j += 4) {
            int s0 = __ldg(&g_csr_src[j]);
            int s1 = __ldg(&g_csr_src[j + 1]);
            int s2 = __ldg(&g_csr_src[j + 2]);
            int s3 = __ldg(&g_csr_src[j + 3]);
            float c0 = __ldg(&g_inv_out[s0]);
            float c1 = __ldg(&g_inv_out[s1]);
            float c2 = __ldg(&g_inv_out[s2]);
            float c3 = __ldg(&g_inv_out[s3]);
            uint2 u0 = __ldg(hb + (size_t)s0 * D8 + lane);
            uint2 u1 = __ldg(hb + (size_t)s1 * D8 + lane);
            uint2 u2 = __ldg(hb + (size_t)s2 * D8 + lane);
            uint2 u3 = __ldg(hb + (size_t)s3 * D8 + lane);
            float2 f;
            f = __half22float2(u32_to_h2(u0.x)); a.x += c0 * f.x; a.y += c0 * f.y;
            f = __half22float2(u32_to_h2(u0.y)); a.z += c0 * f.x; a.w += c0 * f.y;
            f = __half22float2(u32_to_h2(u1.x)); a.x += c1 * f.x; a.y += c1 * f.y;
            f = __half22float2(u32_to_h2(u1.y)); a.z += c1 * f.x; a.w += c1 * f.y;
            f = __half22float2(u32_to_h2(u2.x)); a.x += c2 * f.x; a.y += c2 * f.y;
            f = __half22float2(u32_to_h2(u2.y)); a.z += c2 * f.x; a.w += c2 * f.y;
            f = __half22float2(u32_to_h2(u3.x)); a.x += c3 * f.x; a.y += c3 * f.y;
            f = __half22float2(u32_to_h2(u3.y)); a.z += c3 * f.x; a.w += c3 * f.y;
        }
        for (; j < end; j++) {
            int s = __ldg(&g_csr_src[j]);
            float c = __ldg(&g_inv_out[s]);
            uint2 u = __ldg(hb + (size_t)s * D8 + lane);
            float2 f;
            f = __half22float2(u32_to_h2(u.x)); a.x += c * f.x; a.y += c * f.y;
            f = __half22float2(u32_to_h2(u.y)); a.z += c * f.x; a.w += c * f.y;
        }

        float dg  = (float)(end - beg);
        float inv = dg > 0.f ? rsqrtf(dg) : 0.f;
        float4 bb = ((const float4*)b)[lane];
        float4 o  = make_float4(a.x * inv + bb.x, a.y * inv + bb.y,
                                a.z * inv + bb.z, a.w * inv + bb.w);
        ((float4*)(out + (size_t)warp * D))[lane] = o;
    }

    // restore zero-invariant for the next graph replay
    if (lane == 30) {
        g_deg_in_i[warp]  = 0;
        g_deg_out_i[warp] = 0;
    }
}

extern "C" void kernel_launch(void* const* d_in, const int* in_sizes, int n_in,
                              void* d_out, int out_size) {
    const float* x   = (const float*)d_in[0];
    const float* W   = (const float*)d_in[1];
    const float* b   = (const float*)d_in[2];
    const int*   src = (const int*)d_in[3];
    const int*   dst = (const int*)d_in[4];
    float* out = (float*)d_out;
    const int E = in_sizes[3];

    static bool attr_set = false;
    if (!attr_set) {
        cudaFuncSetAttribute(k_gemm,
                             cudaFuncAttributePreferredSharedMemoryCarveout, 66);
        attr_set = true;
    }

    cudaStream_t s2;
    cudaStreamCreateWithFlags(&s2, cudaStreamNonBlocking);
    cudaEvent_t ev_root, ev_gemm;
    cudaEventCreateWithFlags(&ev_root, cudaEventDisableTiming);
    cudaEventCreateWithFlags(&ev_gemm, cudaEventDisableTiming);

    // s2: gemm has NO data dependencies -> starts at graph root.
    cudaEventRecord(ev_root, 0);
    cudaStreamWaitEvent(s2, ev_root, 0);
    k_gemm<<<(N_NODES + TILE_ROWS - 1) / TILE_ROWS, dim3(TX, TY), 0, s2>>>(x, W);
    cudaEventRecord(ev_gemm, s2);

    // main: deg -> inv_out -> scan -> fill (all overlapped with gemm)
    k_deg<<<(E + 255) / 256, 256>>>(src, dst, E);
    k_inv<<<(N_NODES + 255) / 256, 256>>>();
    k_scan1<<<NBLK, 256>>>();
    k_scan23<<<NBLK, 256>>>(E);
    k_fill<<<(E + 255) / 256, 256>>>(src, dst, E);

    cudaStreamWaitEvent(0, ev_gemm, 0);
    long long agg_threads = (long long)N_NODES * 32;
    k_agg<<<(int)((agg_threads + 255) / 256), 256>>>(b, out);
}

// round 16
// speedup vs baseline: 1.5510x; 1.1466x over previous
#include <cuda_runtime.h>
#include <cuda_fp16.h>
#include <mma.h>
#include <cstdint>

using namespace nvcuda;

#define N_NODES 50000
#define MAX_E   800000
#define D 96
#define D4 (D/4)
#define D8 (D/4)                             // 24 uint2 (4 halves) per row
#define GROWS 96                             // rows per gemm block
#define GT 192                               // gemm threads (6 warps)
#define NBLK ((N_NODES + 255) / 256)         // 196 scan blocks

// ---- device scratch (zero-init at load; k_agg restores counter zeros) ----
__device__ int    g_deg_out_i[N_NODES];
__device__ int    g_deg_in_i[N_NODES];
__device__ float  g_inv_out[N_NODES];
__device__ int    g_row_ptr[N_NODES + 1];
__device__ int    g_fill[N_NODES];
__device__ int    g_bsum[256];
__device__ int    g_csr_src[MAX_E];
__device__ __half g_hh[(size_t)N_NODES * D]; // h = x@W, fp16 (unscaled)

// bit-cast helpers (register moves only)
__device__ __forceinline__ unsigned h2_to_u32(__half2 h) {
    return *reinterpret_cast<unsigned*>(&h);
}
__device__ __forceinline__ __half2 u32_to_h2(unsigned u) {
    return *reinterpret_cast<__half2*>(&u);
}

// ---- kernel: degree counts (counters pre-zeroed by invariant) ----
__global__ void k_deg(const int* __restrict__ src,
                      const int* __restrict__ dst, int E) {
    int e = blockIdx.x * blockDim.x + threadIdx.x;
    if (e < E) {
        atomicAdd(&g_deg_out_i[src[e]], 1);
        atomicAdd(&g_deg_in_i[dst[e]], 1);
    }
}

// ---- kernel: inv_out = rsqrt(deg_out) ----
__global__ void k_inv() {
    int i = blockIdx.x * blockDim.x + threadIdx.x;
    if (i < N_NODES) {
        float dg = (float)g_deg_out_i[i];
        g_inv_out[i] = dg > 0.f ? rsqrtf(dg) : 0.f;
    }
}

// ---- scan step 1: per-block exclusive scan of deg_in ----
__global__ void k_scan1() {
    __shared__ int sh[256];
    int i = blockIdx.x * 256 + threadIdx.x;
    int v = (i < N_NODES) ? g_deg_in_i[i] : 0;
    sh[threadIdx.x] = v;
    __syncthreads();
    #pragma unroll
    for (int off = 1; off < 256; off <<= 1) {
        int t = (threadIdx.x >= off) ? sh[threadIdx.x - off] : 0;
        __syncthreads();
        sh[threadIdx.x] += t;
        __syncthreads();
    }
    if (i < N_NODES) g_row_ptr[i] = sh[threadIdx.x] - v;
    if (threadIdx.x == 255) g_bsum[blockIdx.x] = sh[255];
}

// ---- scan steps 2+3 fused: every block scans the 196 block sums itself ----
__global__ void k_scan23(int E) {
    __shared__ int sh[256];
    int t = threadIdx.x;
    int v = (t < NBLK) ? g_bsum[t] : 0;
    sh[t] = v;
    __syncthreads();
    #pragma unroll
    for (int off = 1; off < 256; off <<= 1) {
        int u = (t >= off) ? sh[t - off] : 0;
        __syncthreads();
        sh[t] += u;
        __syncthreads();
    }
    int base = (blockIdx.x > 0) ? sh[blockIdx.x - 1] : 0;

    int i = blockIdx.x * 256 + t;
    if (i < N_NODES) {
        int p = g_row_ptr[i] + base;
        g_row_ptr[i] = p;
        g_fill[i] = p;
    }
    if (i == 0) g_row_ptr[N_NODES] = E;
}

// ---- kernel: bucket edges by dst ----
__global__ void k_fill(const int* __restrict__ src,
                       const int* __restrict__ dst, int E) {
    int e = blockIdx.x * blockDim.x + threadIdx.x;
    if (e < E) {
        int d = dst[e];
        int pos = atomicAdd(&g_fill[d], 1);
        g_csr_src[pos] = src[e];
    }
}

// ---- kernel: h = x@W via fp16 HMMA (fp32 accumulate), no dependencies ----
// 96 rows/block, 6 warps; warp w owns rows [16w,16w+16) x all 96 cols.
// smem: halves of x and W during mma; SAME buffer reused as float[96][96]
// for the accumulator staging in the epilogue (exactly 36864 B both ways).
__global__ __launch_bounds__(GT)
void k_gemm(const float* __restrict__ x, const float* __restrict__ Wg) {
    __shared__ __align__(16) char sbuf[D * D * 4];   // 36864 B
    __half* xs_h = (__half*)sbuf;                    // [96][96] halves
    __half* ws_h = (__half*)(sbuf + D * D * 2);      // [96][96] halves
    float*  Sf   = (float*)sbuf;                     // [96][96] floats (epilogue)

    const int tid = threadIdx.x;
    const int rbase = blockIdx.x * GROWS;

    // stage x (zero-padded) and W, converting fp32 -> fp16
    for (int i = tid; i < GROWS * D4; i += GT) {
        int r = i / D4, c = i % D4;
        int g = rbase + r;
        float4 v = make_float4(0.f, 0.f, 0.f, 0.f);
        if (g < N_NODES) v = ((const float4*)(x + (size_t)g * D))[c];
        uint2 ux;
        ux.x = h2_to_u32(__floats2half2_rn(v.x, v.y));
        ux.y = h2_to_u32(__floats2half2_rn(v.z, v.w));
        ((uint2*)xs_h)[i] = ux;

        float4 wv = ((const float4*)Wg)[i];
        uint2 uw;
        uw.x = h2_to_u32(__floats2half2_rn(wv.x, wv.y));
        uw.y = h2_to_u32(__floats2half2_rn(wv.z, wv.w));
        ((uint2*)ws_h)[i] = uw;
    }
    __syncthreads();

    const int warp = tid >> 5;

    wmma::fragment<wmma::accumulator, 16, 16, 16, float> acc[6];
    #pragma unroll
    for (int j = 0; j < 6; j++) wmma::fill_fragment(acc[j], 0.0f);

    #pragma unroll
    for (int k = 0; k < 6; k++) {
        wmma::fragment<wmma::matrix_a, 16, 16, 16, __half, wmma::row_major> af;
        wmma::load_matrix_sync(af, xs_h + warp * 16 * D + k * 16, D);
        #pragma unroll
        for (int j = 0; j < 6; j++) {
            wmma::fragment<wmma::matrix_b, 16, 16, 16, __half, wmma::row_major> bf;
            wmma::load_matrix_sync(bf, ws_h + (k * 16) * D + j * 16, D);
            wmma::mma_sync(acc[j], af, bf, acc[j]);
        }
    }

    __syncthreads();   // all warps done reading xs_h/ws_h
    #pragma unroll
    for (int j = 0; j < 6; j++)
        wmma::store_matrix_sync(Sf + warp * 16 * D + j * 16, acc[j], D,
                                wmma::mem_row_major);
    __syncthreads();

    // epilogue: float smem -> fp16 global h
    for (int i = tid; i < GROWS * D4; i += GT) {
        int r = i / D4, c = i % D4;
        int row = rbase + r;
        if (row < N_NODES) {
            float4 v = ((float4*)Sf)[i];
            uint2 u;
            u.x = h2_to_u32(__floats2half2_rn(v.x, v.y));
            u.y = h2_to_u32(__floats2half2_rn(v.z, v.w));
            ((uint2*)(g_hh + (size_t)row * D))[c] = u;
        }
    }
}

// ---- kernel: aggregate per dst: out[d] = inv_in[d]*Σ inv_out[s]*h[s] + b ----
__global__ __launch_bounds__(256)
void k_agg(const float* __restrict__ b, float* __restrict__ out) {
    int warp = (blockIdx.x * blockDim.x + threadIdx.x) >> 5;
    int lane = threadIdx.x & 31;
    if (warp >= N_NODES) return;

    int beg = g_row_ptr[warp];
    int end = g_row_ptr[warp + 1];

    if (lane < D8) {
        float4 a = make_float4(0.f, 0.f, 0.f, 0.f);
        const uint2* hb = (const uint2*)g_hh;   // 24 uint2 (4 halves) per row
        int j = beg;
        for (; j + 3 < end; j += 4) {
            int s0 = __ldg(&g_csr_src[j]);
            int s1 = __ldg(&g_csr_src[j + 1]);
            int s2 = __ldg(&g_csr_src[j + 2]);
            int s3 = __ldg(&g_csr_src[j + 3]);
            float c0 = __ldg(&g_inv_out[s0]);
            float c1 = __ldg(&g_inv_out[s1]);
            float c2 = __ldg(&g_inv_out[s2]);
            float c3 = __ldg(&g_inv_out[s3]);
            uint2 u0 = __ldg(hb + (size_t)s0 * D8 + lane);
            uint2 u1 = __ldg(hb + (size_t)s1 * D8 + lane);
            uint2 u2 = __ldg(hb + (size_t)s2 * D8 + lane);
            uint2 u3 = __ldg(hb + (size_t)s3 * D8 + lane);
            float2 f;
            f = __half22float2(u32_to_h2(u0.x)); a.x += c0 * f.x; a.y += c0 * f.y;
            f = __half22float2(u32_to_h2(u0.y)); a.z += c0 * f.x; a.w += c0 * f.y;
            f = __half22float2(u32_to_h2(u1.x)); a.x += c1 * f.x; a.y += c1 * f.y;
            f = __half22float2(u32_to_h2(u1.y)); a.z += c1 * f.x; a.w += c1 * f.y;
            f = __half22float2(u32_to_h2(u2.x)); a.x += c2 * f.x; a.y += c2 * f.y;
            f = __half22float2(u32_to_h2(u2.y)); a.z += c2 * f.x; a.w += c2 * f.y;
            f = __half22float2(u32_to_h2(u3.x)); a.x += c3 * f.x; a.y += c3 * f.y;
            f = __half22float2(u32_to_h2(u3.y)); a.z += c3 * f.x; a.w += c3 * f.y;
        }
        for (; j < end; j++) {
            int s = __ldg(&g_csr_src[j]);
            float c = __ldg(&g_inv_out[s]);
            uint2 u = __ldg(hb + (size_t)s * D8 + lane);
            float2 f;
            f = __half22float2(u32_to_h2(u.x)); a.x += c * f.x; a.y += c * f.y;
            f = __half22float2(u32_to_h2(u.y)); a.z += c * f.x; a.w += c * f.y;
        }

        float dg  = (float)(end - beg);
        float inv = dg > 0.f ? rsqrtf(dg) : 0.f;
        float4 bb = ((const float4*)b)[lane];
        float4 o  = make_float4(a.x * inv + bb.x, a.y * inv + bb.y,
                                a.z * inv + bb.z, a.w * inv + bb.w);
        ((float4*)(out + (size_t)warp * D))[lane] = o;
    }

    // restore zero-invariant for the next graph replay
    if (lane == 30) {
        g_deg_in_i[warp]  = 0;
        g_deg_out_i[warp] = 0;
    }
}

extern "C" void kernel_launch(void* const* d_in, const int* in_sizes, int n_in,
                              void* d_out, int out_size) {
    const float* x   = (const float*)d_in[0];
    const float* W   = (const float*)d_in[1];
    const float* b   = (const float*)d_in[2];
    const int*   src = (const int*)d_in[3];
    const int*   dst = (const int*)d_in[4];
    float* out = (float*)d_out;
    const int E = in_sizes[3];

    cudaStream_t s2;
    cudaStreamCreateWithFlags(&s2, cudaStreamNonBlocking);
    cudaEvent_t ev_root, ev_gemm;
    cudaEventCreateWithFlags(&ev_root, cudaEventDisableTiming);
    cudaEventCreateWithFlags(&ev_gemm, cudaEventDisableTiming);

    // s2: gemm has NO data dependencies -> starts at graph root.
    cudaEventRecord(ev_root, 0);
    cudaStreamWaitEvent(s2, ev_root, 0);
    k_gemm<<<(N_NODES + GROWS - 1) / GROWS, GT, 0, s2>>>(x, W);
    cudaEventRecord(ev_gemm, s2);

    // main: deg -> inv_out -> scan -> fill (all overlapped with gemm)
    k_deg<<<(E + 255) / 256, 256>>>(src, dst, E);
    k_inv<<<(N_NODES + 255) / 256, 256>>>();
    k_scan1<<<NBLK, 256>>>();
    k_scan23<<<NBLK, 256>>>(E);
    k_fill<<<(E + 255) / 256, 256>>>(src, dst, E);

    cudaStreamWaitEvent(0, ev_gemm, 0);
    long long agg_threads = (long long)N_NODES * 32;
    k_agg<<<(int)((agg_threads + 255) / 256), 256>>>(b, out);
}

// round 17
// speedup vs baseline: 1.6283x; 1.0498x over previous
#include <cuda_runtime.h>
#include <cuda_fp16.h>
#include <mma.h>
#include <cstdint>

using namespace nvcuda;

#define N_NODES 50000
#define MAX_E   800000
#define D 96
#define D4 (D/4)
#define D8 (D/4)                             // 24 uint2 (4 halves) per row
#define GROWS 96                             // rows per gemm block
#define GT 192                               // gemm threads (6 warps)
#define NBLK ((N_NODES + 255) / 256)         // 196 scan blocks

// ---- device scratch (zero-init at load; k_agg restores counter zeros) ----
__device__ int    g_deg_out_i[N_NODES];
__device__ int    g_deg_in_i[N_NODES];
__device__ float  g_inv_out[N_NODES];
__device__ int    g_row_ptr[N_NODES + 1];    // scan1: local prefix; fill: +base
__device__ int    g_fill[N_NODES];           // local cursors
__device__ int    g_bsum[256];               // per-scan-block sums
__device__ int    g_csr_src[MAX_E];
__device__ __half g_hh[(size_t)N_NODES * D]; // h = x@W, fp16 (unscaled)

// bit-cast helpers (register moves only)
__device__ __forceinline__ unsigned h2_to_u32(__half2 h) {
    return *reinterpret_cast<unsigned*>(&h);
}
__device__ __forceinline__ __half2 u32_to_h2(unsigned u) {
    return *reinterpret_cast<__half2*>(&u);
}

// ---- kernel: degree counts, 2 edges/thread (counters pre-zeroed) ----
__global__ void k_deg(const int* __restrict__ src,
                      const int* __restrict__ dst, int E) {
    int e = (blockIdx.x * blockDim.x + threadIdx.x) * 2;
    if (e + 1 < E) {
        int2 s = *(const int2*)(src + e);
        int2 d = *(const int2*)(dst + e);
        atomicAdd(&g_deg_out_i[s.x], 1);
        atomicAdd(&g_deg_out_i[s.y], 1);
        atomicAdd(&g_deg_in_i[d.x], 1);
        atomicAdd(&g_deg_in_i[d.y], 1);
    } else if (e < E) {
        atomicAdd(&g_deg_out_i[src[e]], 1);
        atomicAdd(&g_deg_in_i[dst[e]], 1);
    }
}

// ---- scan1 (+ fused inv_out): local exclusive scan of deg_in ----
__global__ void k_scan1() {
    __shared__ int sh[256];
    int i = blockIdx.x * 256 + threadIdx.x;

    // fused side-work: inv_out = rsqrt(deg_out)
    if (i < N_NODES) {
        float dg = (float)g_deg_out_i[i];
        g_inv_out[i] = dg > 0.f ? rsqrtf(dg) : 0.f;
    }

    int v = (i < N_NODES) ? g_deg_in_i[i] : 0;
    sh[threadIdx.x] = v;
    __syncthreads();
    #pragma unroll
    for (int off = 1; off < 256; off <<= 1) {
        int t = (threadIdx.x >= off) ? sh[threadIdx.x - off] : 0;
        __syncthreads();
        sh[threadIdx.x] += t;
        __syncthreads();
    }
    if (i < N_NODES) {
        int p = sh[threadIdx.x] - v;     // LOCAL exclusive prefix
        g_row_ptr[i] = p;
        g_fill[i]    = p;                // local cursor
    }
    if (threadIdx.x == 255) g_bsum[blockIdx.x] = sh[255];
}

// ---- fill: re-scan block sums in smem, bucket edges, finalize row_ptr ----
__global__ void k_fill(const int* __restrict__ src,
                       const int* __restrict__ dst, int E) {
    __shared__ int sh[256];               // inclusive scan of g_bsum
    int t = threadIdx.x;
    int v = (t < NBLK) ? g_bsum[t] : 0;
    sh[t] = v;
    __syncthreads();
    #pragma unroll
    for (int off = 1; off < 256; off <<= 1) {
        int u = (t >= off) ? sh[t - off] : 0;
        __syncthreads();
        sh[t] += u;
        __syncthreads();
    }
    // sbase[b] = (b>0) ? sh[b-1] : 0

    // blocks 0..NBLK-1 finalize row_ptr in place (for k_agg)
    if ((int)blockIdx.x < NBLK) {
        int i = blockIdx.x * 256 + t;
        int base = (blockIdx.x > 0) ? sh[blockIdx.x - 1] : 0;
        if (i < N_NODES) g_row_ptr[i] += base;
        if (i == 0) g_row_ptr[N_NODES] = E;
    }

    // all blocks: bucket edges
    int e = blockIdx.x * 256 + t;
    if (e < E) {
        int d = dst[e];
        int pos  = atomicAdd(&g_fill[d], 1);              // local pos
        int b    = d >> 8;
        int base = (b > 0) ? sh[b - 1] : 0;
        g_csr_src[pos + base] = src[e];
    }
}

// ---- kernel: h = x@W via fp16 HMMA (fp32 accumulate), no dependencies ----
__global__ __launch_bounds__(GT)
void k_gemm(const float* __restrict__ x, const float* __restrict__ Wg) {
    __shared__ __align__(16) char sbuf[D * D * 4];   // 36864 B
    __half* xs_h = (__half*)sbuf;                    // [96][96] halves
    __half* ws_h = (__half*)(sbuf + D * D * 2);      // [96][96] halves
    float*  Sf   = (float*)sbuf;                     // [96][96] floats (epilogue)

    const int tid = threadIdx.x;
    const int rbase = blockIdx.x * GROWS;

    for (int i = tid; i < GROWS * D4; i += GT) {
        int r = i / D4, c = i % D4;
        int g = rbase + r;
        float4 v = make_float4(0.f, 0.f, 0.f, 0.f);
        if (g < N_NODES) v = ((const float4*)(x + (size_t)g * D))[c];
        uint2 ux;
        ux.x = h2_to_u32(__floats2half2_rn(v.x, v.y));
        ux.y = h2_to_u32(__floats2half2_rn(v.z, v.w));
        ((uint2*)xs_h)[i] = ux;

        float4 wv = ((const float4*)Wg)[i];
        uint2 uw;
        uw.x = h2_to_u32(__floats2half2_rn(wv.x, wv.y));
        uw.y = h2_to_u32(__floats2half2_rn(wv.z, wv.w));
        ((uint2*)ws_h)[i] = uw;
    }
    __syncthreads();

    const int warp = tid >> 5;

    wmma::fragment<wmma::accumulator, 16, 16, 16, float> acc[6];
    #pragma unroll
    for (int j = 0; j < 6; j++) wmma::fill_fragment(acc[j], 0.0f);

    #pragma unroll
    for (int k = 0; k < 6; k++) {
        wmma::fragment<wmma::matrix_a, 16, 16, 16, __half, wmma::row_major> af;
        wmma::load_matrix_sync(af, xs_h + warp * 16 * D + k * 16, D);
        #pragma unroll
        for (int j = 0; j < 6; j++) {
            wmma::fragment<wmma::matrix_b, 16, 16, 16, __half, wmma::row_major> bf;
            wmma::load_matrix_sync(bf, ws_h + (k * 16) * D + j * 16, D);
            wmma::mma_sync(acc[j], af, bf, acc[j]);
        }
    }

    __syncthreads();
    #pragma unroll
    for (int j = 0; j < 6; j++)
        wmma::store_matrix_sync(Sf + warp * 16 * D + j * 16, acc[j], D,
                                wmma::mem_row_major);
    __syncthreads();

    for (int i = tid; i < GROWS * D4; i += GT) {
        int r = i / D4, c = i % D4;
        int row = rbase + r;
        if (row < N_NODES) {
            float4 v = ((float4*)Sf)[i];
            uint2 u;
            u.x = h2_to_u32(__floats2half2_rn(v.x, v.y));
            u.y = h2_to_u32(__floats2half2_rn(v.z, v.w));
            ((uint2*)(g_hh + (size_t)row * D))[c] = u;
        }
    }
}

// ---- kernel: aggregate per dst: out[d] = inv_in[d]*Σ inv_out[s]*h[s] + b ----
__global__ __launch_bounds__(256)
void k_agg(const float* __restrict__ b, float* __restrict__ out) {
    int warp = (blockIdx.x * blockDim.x + threadIdx.x) >> 5;
    int lane = threadIdx.x & 31;
    if (warp >= N_NODES) return;

    int beg = g_row_ptr[warp];
    int end = g_row_ptr[warp + 1];

    if (lane < D8) {
        float4 a = make_float4(0.f, 0.f, 0.f, 0.f);
        const uint2* hb = (const uint2*)g_hh;
        int j = beg;
        for (; j + 3 < end; j += 4) {
            int s0 = __ldg(&g_csr_src[j]);
            int s1 = __ldg(&g_csr_src[j + 1]);
            int s2 = __ldg(&g_csr_src[j + 2]);
            int s3 = __ldg(&g_csr_src[j + 3]);
            float c0 = __ldg(&g_inv_out[s0]);
            float c1 = __ldg(&g_inv_out[s1]);
            float c2 = __ldg(&g_inv_out[s2]);
            float c3 = __ldg(&g_inv_out[s3]);
            uint2 u0 = __ldg(hb + (size_t)s0 * D8 + lane);
            uint2 u1 = __ldg(hb + (size_t)s1 * D8 + lane);
            uint2 u2 = __ldg(hb + (size_t)s2 * D8 + lane);
            uint2 u3 = __ldg(hb + (size_t)s3 * D8 + lane);
            float2 f;
            f = __half22float2(u32_to_h2(u0.x)); a.x += c0 * f.x; a.y += c0 * f.y;
            f = __half22float2(u32_to_h2(u0.y)); a.z += c0 * f.x; a.w += c0 * f.y;
            f = __half22float2(u32_to_h2(u1.x)); a.x += c1 * f.x; a.y += c1 * f.y;
            f = __half22float2(u32_to_h2(u1.y)); a.z += c1 * f.x; a.w += c1 * f.y;
            f = __half22float2(u32_to_h2(u2.x)); a.x += c2 * f.x; a.y += c2 * f.y;
            f = __half22float2(u32_to_h2(u2.y)); a.z += c2 * f.x; a.w += c2 * f.y;
            f = __half22float2(u32_to_h2(u3.x)); a.x += c3 * f.x; a.y += c3 * f.y;
            f = __half22float2(u32_to_h2(u3.y)); a.z += c3 * f.x; a.w += c3 * f.y;
        }
        for (; j < end; j++) {
            int s = __ldg(&g_csr_src[j]);
            float c = __ldg(&g_inv_out[s]);
            uint2 u = __ldg(hb + (size_t)s * D8 + lane);
            float2 f;
            f = __half22float2(u32_to_h2(u.x)); a.x += c * f.x; a.y += c * f.y;
            f = __half22float2(u32_to_h2(u.y)); a.z += c * f.x; a.w += c * f.y;
        }

        float dg  = (float)(end - beg);
        float inv = dg > 0.f ? rsqrtf(dg) : 0.f;
        float4 bb = ((const float4*)b)[lane];
        float4 o  = make_float4(a.x * inv + bb.x, a.y * inv + bb.y,
                                a.z * inv + bb.z, a.w * inv + bb.w);
        ((float4*)(out + (size_t)warp * D))[lane] = o;
    }

    // restore zero-invariant for the next graph replay
    if (lane == 30) {
        g_deg_in_i[warp]  = 0;
        g_deg_out_i[warp] = 0;
    }
}

extern "C" void kernel_launch(void* const* d_in, const int* in_sizes, int n_in,
                              void* d_out, int out_size) {
    const float* x   = (const float*)d_in[0];
    const float* W   = (const float*)d_in[1];
    const float* b   = (const float*)d_in[2];
    const int*   src = (const int*)d_in[3];
    const int*   dst = (const int*)d_in[4];
    float* out = (float*)d_out;
    const int E = in_sizes[3];

    cudaStream_t s2;
    cudaStreamCreateWithFlags(&s2, cudaStreamNonBlocking);
    cudaEvent_t ev_root, ev_gemm;
    cudaEventCreateWithFlags(&ev_root, cudaEventDisableTiming);
    cudaEventCreateWithFlags(&ev_gemm, cudaEventDisableTiming);

    // s2: gemm has NO data dependencies -> starts at graph root.
    cudaEventRecord(ev_root, 0);
    cudaStreamWaitEvent(s2, ev_root, 0);
    k_gemm<<<(N_NODES + GROWS - 1) / GROWS, GT, 0, s2>>>(x, W);
    cudaEventRecord(ev_gemm, s2);

    // main: deg -> scan1(+inv) -> fill (scan23 folded into fill prologue)
    int deg_blocks = (E / 2 + 255) / 256 + 1;
    k_deg<<<deg_blocks, 256>>>(src, dst, E);
    k_scan1<<<NBLK, 256>>>();
    k_fill<<<(E + 255) / 256, 256>>>(src, dst, E);

    cudaStreamWaitEvent(0, ev_gemm, 0);
    long long agg_threads = (long long)N_NODES * 32;
    k_agg<<<(int)((agg_threads + 255) / 256), 256>>>(b, out);
}